// round 1
// baseline (speedup 1.0000x reference)
#include <cuda_runtime.h>
#include <math.h>

#define B_   2
#define T_   2048
#define D_   2048
#define NH   16
#define NKV  8
#define HD   128
#define KVD  (NKV*HD)   // 1024

// Scratch (device globals — allocation-free per harness rules)
__device__ float g_Q[(size_t)B_ * T_ * D_];            //  33.5 MB
__device__ float g_K[(size_t)B_ * T_ * KVD];           //  16.8 MB
__device__ float g_V[(size_t)B_ * T_ * KVD];           //  16.8 MB
__device__ float g_S[(size_t)B_ * NH * T_ * T_];       // 536.9 MB
__device__ float g_O[(size_t)B_ * T_ * D_];            //  33.5 MB

// ---------------------------------------------------------------------------
// Tiled SGEMM body: C[M,N] = alpha * A op(B)
//   NT=true : C[i,j] = sum_k A[i*lda+k] * B[j*ldb+k]   (both K-contiguous)
//   NT=false: C[i,j] = sum_k A[i*lda+k] * B[k*ldb+j]
// Block tile 128x128, K-step 16, 256 threads, 8x8 per-thread micro-tile.
// Requires M,N multiples of 128 and K multiple of 16 (true for all calls).
// ---------------------------------------------------------------------------
template<bool NT>
__device__ __forceinline__ void gemm_body(
    const float* __restrict__ A, int lda,
    const float* __restrict__ B, int ldb,
    float* __restrict__ C, int ldc,
    int K, float alpha)
{
    __shared__ __align__(16) float As[16][128];
    __shared__ __align__(16) float Bs[16][128];

    const int tid = threadIdx.x;          // 0..255
    const int tx  = tid & 15;             // 0..15
    const int ty  = tid >> 4;             // 0..15
    const int m0  = blockIdx.y * 128;
    const int n0  = blockIdx.x * 128;

    float acc[8][8];
    #pragma unroll
    for (int i = 0; i < 8; ++i)
        #pragma unroll
        for (int j = 0; j < 8; ++j)
            acc[i][j] = 0.0f;

    for (int kt = 0; kt < K; kt += 16) {
        #pragma unroll
        for (int it = 0; it < 2; ++it) {
            const int f = tid + it * 256;          // 0..511
            {   // A tile: 128 rows x 16 cols, store transposed As[k][m]
                const int row = f >> 2;
                const int c4  = (f & 3) << 2;
                float4 v = *(const float4*)(A + (size_t)(m0 + row) * lda + kt + c4);
                As[c4 + 0][row] = v.x;
                As[c4 + 1][row] = v.y;
                As[c4 + 2][row] = v.z;
                As[c4 + 3][row] = v.w;
            }
            if (NT) {   // B tile: 128 rows (N) x 16 cols (K), store Bs[k][n]
                const int row = f >> 2;
                const int c4  = (f & 3) << 2;
                float4 v = *(const float4*)(B + (size_t)(n0 + row) * ldb + kt + c4);
                Bs[c4 + 0][row] = v.x;
                Bs[c4 + 1][row] = v.y;
                Bs[c4 + 2][row] = v.z;
                Bs[c4 + 3][row] = v.w;
            } else {    // B tile: 16 rows (K) x 128 cols (N), direct Bs[k][n]
                const int kr = f >> 5;
                const int c4 = (f & 31) << 2;
                float4 v = *(const float4*)(B + (size_t)(kt + kr) * ldb + n0 + c4);
                *(float4*)&Bs[kr][c4] = v;
            }
        }
        __syncthreads();

        #pragma unroll
        for (int k = 0; k < 16; ++k) {
            float a[8], b[8];
            *(float4*)(a    ) = *(const float4*)&As[k][ty * 8];
            *(float4*)(a + 4) = *(const float4*)&As[k][ty * 8 + 4];
            *(float4*)(b    ) = *(const float4*)&Bs[k][tx * 8];
            *(float4*)(b + 4) = *(const float4*)&Bs[k][tx * 8 + 4];
            #pragma unroll
            for (int i = 0; i < 8; ++i)
                #pragma unroll
                for (int j = 0; j < 8; ++j)
                    acc[i][j] += a[i] * b[j];
        }
        __syncthreads();
    }

    #pragma unroll
    for (int i = 0; i < 8; ++i) {
        float* cp = C + (size_t)(m0 + ty * 8 + i) * ldc + n0 + tx * 8;
        float4 o0 = make_float4(acc[i][0] * alpha, acc[i][1] * alpha,
                                acc[i][2] * alpha, acc[i][3] * alpha);
        float4 o1 = make_float4(acc[i][4] * alpha, acc[i][5] * alpha,
                                acc[i][6] * alpha, acc[i][7] * alpha);
        *(float4*)(cp)     = o0;
        *(float4*)(cp + 4) = o1;
    }
}

// Plain NT GEMM (projections, output projection)
__global__ void __launch_bounds__(256)
gemm_nt_kernel(const float* __restrict__ A, int lda,
               const float* __restrict__ B, int ldb,
               float* __restrict__ C, int ldc, int K, float alpha)
{
    gemm_body<true>(A, lda, B, ldb, C, ldc, K, alpha);
}

// Scores: S[z] = (Q_z @ K_z^T) / sqrt(d), z = b*16 + hq, kv = hq/2
__global__ void __launch_bounds__(256)
scores_kernel(const float* __restrict__ Q, const float* __restrict__ Kb,
              float* __restrict__ S, float alpha)
{
    const int z  = blockIdx.z;
    const int b  = z >> 4;
    const int hq = z & 15;
    const int kv = hq >> 1;
    gemm_body<true>(Q  + (size_t)b * T_ * D_  + hq * HD, D_,
                    Kb + (size_t)b * T_ * KVD + kv * HD, KVD,
                    S  + (size_t)z * T_ * T_,            T_,
                    HD, alpha);
}

// PV: O_z = P_z @ V_z  (NN: V is [s, kv*128+d], d contiguous)
__global__ void __launch_bounds__(256)
pv_kernel(const float* __restrict__ S, const float* __restrict__ V,
          float* __restrict__ O)
{
    const int z  = blockIdx.z;
    const int b  = z >> 4;
    const int hq = z & 15;
    const int kv = hq >> 1;
    gemm_body<false>(S + (size_t)z * T_ * T_,            T_,
                     V + (size_t)b * T_ * KVD + kv * HD, KVD,
                     O + (size_t)b * T_ * D_  + hq * HD, D_,
                     T_, 1.0f);
}

// Row softmax over length T_, row cached in shared memory (1 read + 1 write)
__global__ void __launch_bounds__(256)
softmax_kernel(float* __restrict__ S)
{
    __shared__ __align__(16) float row[T_];
    __shared__ float red[256];
    const size_t base = (size_t)blockIdx.x * T_;
    const int tid = threadIdx.x;

    float m = -1e30f;
    for (int i = tid; i < T_; i += 256) {
        float v = S[base + i];
        row[i] = v;
        m = fmaxf(m, v);
    }
    red[tid] = m;
    __syncthreads();
    #pragma unroll
    for (int s = 128; s > 0; s >>= 1) {
        if (tid < s) red[tid] = fmaxf(red[tid], red[tid + s]);
        __syncthreads();
    }
    m = red[0];
    __syncthreads();

    float sum = 0.0f;
    for (int i = tid; i < T_; i += 256) {
        float e = __expf(row[i] - m);
        row[i] = e;
        sum += e;
    }
    red[tid] = sum;
    __syncthreads();
    #pragma unroll
    for (int s = 128; s > 0; s >>= 1) {
        if (tid < s) red[tid] += red[tid + s];
        __syncthreads();
    }
    const float inv = 1.0f / red[0];
    for (int i = tid; i < T_; i += 256)
        S[base + i] = row[i] * inv;
}

extern "C" void kernel_launch(void* const* d_in, const int* in_sizes, int n_in,
                              void* d_out, int out_size)
{
    (void)in_sizes; (void)n_in; (void)out_size;
    const float* x  = (const float*)d_in[0];
    const float* Wq = (const float*)d_in[1];
    const float* Wk = (const float*)d_in[2];
    const float* Wv = (const float*)d_in[3];
    const float* Wo = (const float*)d_in[4];
    float* out = (float*)d_out;

    float *Q, *K, *V, *S, *O;
    cudaGetSymbolAddress((void**)&Q, g_Q);
    cudaGetSymbolAddress((void**)&K, g_K);
    cudaGetSymbolAddress((void**)&V, g_V);
    cudaGetSymbolAddress((void**)&S, g_S);
    cudaGetSymbolAddress((void**)&O, g_O);

    const dim3 thr(256);
    const int BT = B_ * T_;                   // 4096 tokens
    const float inv_scale = 1.0f / sqrtf((float)HD);

    // Projections: y = x @ W^T
    gemm_nt_kernel<<<dim3(D_  / 128, BT / 128), thr>>>(x, D_, Wq, D_, Q, D_,  D_, 1.0f);
    gemm_nt_kernel<<<dim3(KVD / 128, BT / 128), thr>>>(x, D_, Wk, D_, K, KVD, D_, 1.0f);
    gemm_nt_kernel<<<dim3(KVD / 128, BT / 128), thr>>>(x, D_, Wv, D_, V, KVD, D_, 1.0f);

    // Attention
    scores_kernel<<<dim3(T_ / 128, T_ / 128, B_ * NH), thr>>>(Q, K, S, inv_scale);
    softmax_kernel<<<B_ * NH * T_, thr>>>(S);
    pv_kernel<<<dim3(1, T_ / 128, B_ * NH), thr>>>(S, V, O);

    // Output projection
    gemm_nt_kernel<<<dim3(D_ / 128, BT / 128), thr>>>(O, D_, Wo, D_, out, D_, D_, 1.0f);
}

// round 3
// speedup vs baseline: 2.5778x; 2.5778x over previous
#include <cuda_runtime.h>
#include <cstdint>
#include <math.h>

#define B_   2
#define T_   2048
#define D_   2048
#define NH   16
#define NKV  8
#define HD   128
#define KVD  1024
#define BT   4096

// ---------------- scratch (device globals; allocation-free) ----------------
__device__ float g_xr [(size_t)BT  * D_ ];   // tf32-rounded inputs
__device__ float g_Wqr[(size_t)D_  * D_ ];
__device__ float g_Wkr[(size_t)KVD * D_ ];
__device__ float g_Wvr[(size_t)KVD * D_ ];
__device__ float g_Wor[(size_t)D_  * D_ ];
__device__ float g_Q  [(size_t)BT  * D_ ];
__device__ float g_K  [(size_t)BT  * KVD];
__device__ float g_V  [(size_t)BT  * KVD];
__device__ float g_Vt [(size_t)BT  * KVD];   // [b][d(1024)][t(2048)]
__device__ float g_S  [(size_t)B_ * NH * T_ * T_];
__device__ float g_O  [(size_t)BT  * D_ ];

// ---------------- helpers ----------------
__device__ __forceinline__ uint32_t smem_u32(const void* p) {
    uint32_t a;
    asm("{ .reg .u64 t; cvta.to.shared.u64 t, %1; cvt.u32.u64 %0, t; }" : "=r"(a) : "l"(p));
    return a;
}
__device__ __forceinline__ float rtf32(float x) {
    uint32_t r; asm("cvt.rna.tf32.f32 %0, %1;" : "=r"(r) : "f"(x));
    return __uint_as_float(r);
}
__device__ __forceinline__ void cpa16(uint32_t dst, const float* src) {
    asm volatile("cp.async.cg.shared.global [%0], [%1], 16;" :: "r"(dst), "l"(src) : "memory");
}
__device__ __forceinline__ void mma_tf32(float* c, const uint32_t* a, const uint32_t* b) {
    asm volatile("mma.sync.aligned.m16n8k8.row.col.f32.tf32.tf32.f32 "
        "{%0,%1,%2,%3}, {%4,%5,%6,%7}, {%8,%9}, {%0,%1,%2,%3};"
        : "+f"(c[0]), "+f"(c[1]), "+f"(c[2]), "+f"(c[3])
        : "r"(a[0]), "r"(a[1]), "r"(a[2]), "r"(a[3]), "r"(b[0]), "r"(b[1]));
}

// ---------------------------------------------------------------------------
// tf32 MMA GEMM tile: C[128,128] = alpha * A @ B^T  (A, B both K-contiguous)
// K-chunk 16, cp.async double buffer, 8 warps (2x4), warp tile 64x32.
// ---------------------------------------------------------------------------
__device__ __forceinline__ void gemm_mma_body(
    const float* __restrict__ A, int lda,
    const float* __restrict__ B, int ldb,
    float* __restrict__ C, int ldc,
    int K, float alpha, bool round_out, int m0, int n0)
{
    __shared__ float As[2][128][20];   // 16 k-cols + 4 pad (bank-conflict-free)
    __shared__ float Bs[2][128][20];

    const int tid  = threadIdx.x;
    const int lane = tid & 31;
    const int w    = tid >> 5;
    const int g    = lane >> 2;        // groupID 0..7
    const int tg   = lane & 3;         // thread-in-group 0..3
    const int wm   = (w >> 2) << 6;    // warp M offset: 0 / 64
    const int wn   = (w & 3)  << 5;    // warp N offset: 0/32/64/96

    float acc[4][4][4];
    #pragma unroll
    for (int i = 0; i < 4; ++i)
        #pragma unroll
        for (int j = 0; j < 4; ++j)
            #pragma unroll
            for (int r = 0; r < 4; ++r)
                acc[i][j][r] = 0.0f;

    const float* Ab = A + (size_t)m0 * lda;
    const float* Bb = B + (size_t)n0 * ldb;
    const int nk = K >> 4;

    // stage chunk 0
    #pragma unroll
    for (int j = 0; j < 2; ++j) {
        int f = tid + (j << 8);
        int row = f >> 2, c4 = f & 3;
        cpa16(smem_u32(&As[0][row][0]) + c4 * 16, Ab + (size_t)row * lda + c4 * 4);
        cpa16(smem_u32(&Bs[0][row][0]) + c4 * 16, Bb + (size_t)row * ldb + c4 * 4);
    }
    asm volatile("cp.async.commit_group;" ::: "memory");

    for (int i = 0; i < nk; ++i) {
        const int b = i & 1;
        if (i + 1 < nk) {
            const int nb = b ^ 1;
            const int kt = (i + 1) << 4;
            #pragma unroll
            for (int j = 0; j < 2; ++j) {
                int f = tid + (j << 8);
                int row = f >> 2, c4 = f & 3;
                cpa16(smem_u32(&As[nb][row][0]) + c4 * 16, Ab + (size_t)row * lda + kt + c4 * 4);
                cpa16(smem_u32(&Bs[nb][row][0]) + c4 * 16, Bb + (size_t)row * ldb + kt + c4 * 4);
            }
            asm volatile("cp.async.commit_group;" ::: "memory");
            asm volatile("cp.async.wait_group 1;" ::: "memory");
        } else {
            asm volatile("cp.async.wait_group 0;" ::: "memory");
        }
        __syncthreads();

        #pragma unroll
        for (int ks = 0; ks < 2; ++ks) {
            const int k0 = ks << 3;
            uint32_t bf[4][2];
            #pragma unroll
            for (int nt = 0; nt < 4; ++nt) {
                bf[nt][0] = __float_as_uint(Bs[b][wn + (nt << 3) + g][k0 + tg]);
                bf[nt][1] = __float_as_uint(Bs[b][wn + (nt << 3) + g][k0 + tg + 4]);
            }
            #pragma unroll
            for (int mt = 0; mt < 4; ++mt) {
                uint32_t af[4];
                af[0] = __float_as_uint(As[b][wm + (mt << 4) + g    ][k0 + tg]);
                af[1] = __float_as_uint(As[b][wm + (mt << 4) + g + 8][k0 + tg]);
                af[2] = __float_as_uint(As[b][wm + (mt << 4) + g    ][k0 + tg + 4]);
                af[3] = __float_as_uint(As[b][wm + (mt << 4) + g + 8][k0 + tg + 4]);
                #pragma unroll
                for (int nt = 0; nt < 4; ++nt)
                    mma_tf32(acc[mt][nt], af, bf[nt]);
            }
        }
        __syncthreads();
    }

    // epilogue: thread owns rows (g, g+8) of each 16-row mtile, col pair 2*tg
    #pragma unroll
    for (int mt = 0; mt < 4; ++mt) {
        const int r0 = m0 + wm + (mt << 4) + g;
        #pragma unroll
        for (int nt = 0; nt < 4; ++nt) {
            const int cb = n0 + wn + (nt << 3) + (tg << 1);
            float2 v0, v1;
            v0.x = acc[mt][nt][0] * alpha;  v0.y = acc[mt][nt][1] * alpha;
            v1.x = acc[mt][nt][2] * alpha;  v1.y = acc[mt][nt][3] * alpha;
            if (round_out) {
                v0.x = rtf32(v0.x); v0.y = rtf32(v0.y);
                v1.x = rtf32(v1.x); v1.y = rtf32(v1.y);
            }
            *(float2*)(C + (size_t)r0 * ldc + cb)       = v0;
            *(float2*)(C + (size_t)(r0 + 8) * ldc + cb) = v1;
        }
    }
}

// ---------------- kernels ----------------
__global__ void __launch_bounds__(256, 2)
gemm_tc(const float* __restrict__ A, int lda, const float* __restrict__ B, int ldb,
        float* __restrict__ C, int ldc, int K, float alpha, int round_out)
{
    gemm_mma_body(A, lda, B, ldb, C, ldc, K, alpha, round_out != 0,
                  blockIdx.y * 128, blockIdx.x * 128);
}

__global__ void __launch_bounds__(256, 2)
scores_tc(const float* __restrict__ Q, const float* __restrict__ Kb,
          float* __restrict__ S, float alpha)
{
    int z = blockIdx.z, b = z >> 4, hq = z & 15, kv = hq >> 1;
    gemm_mma_body(Q  + (size_t)b * T_ * D_  + hq * HD, D_,
                  Kb + (size_t)b * T_ * KVD + kv * HD, KVD,
                  S  + (size_t)z * T_ * T_,            T_,
                  HD, alpha, false, blockIdx.y * 128, blockIdx.x * 128);
}

__global__ void __launch_bounds__(256, 2)
pv_tc(const float* __restrict__ S, const float* __restrict__ Vt, float* __restrict__ O)
{
    int z = blockIdx.z, b = z >> 4, hq = z & 15, kv = hq >> 1;
    gemm_mma_body(S  + (size_t)z * T_ * T_,                         T_,
                  Vt + (size_t)b * KVD * T_ + (size_t)kv * HD * T_, T_,
                  O  + (size_t)b * T_ * D_  + hq * HD,              D_,
                  T_, 1.0f, true, blockIdx.y * 128, blockIdx.x * 128);
}

__global__ void __launch_bounds__(256)
transpose_v(const float* __restrict__ V, float* __restrict__ Vt)
{
    __shared__ float tile[32][33];
    int b  = blockIdx.z;
    int t0 = blockIdx.x * 32, n0 = blockIdx.y * 32;
    int tx = threadIdx.x & 31, ty = threadIdx.x >> 5;
    const float* src = V  + (size_t)b * T_ * KVD;
    float*       dst = Vt + (size_t)b * KVD * T_;
    #pragma unroll
    for (int j = 0; j < 32; j += 8)
        tile[ty + j][tx] = src[(size_t)(t0 + ty + j) * KVD + n0 + tx];
    __syncthreads();
    #pragma unroll
    for (int j = 0; j < 32; j += 8)
        dst[(size_t)(n0 + ty + j) * T_ + t0 + tx] = tile[tx][ty + j];
}

__global__ void __launch_bounds__(256)
round_inputs(const float4* __restrict__ in, float4* __restrict__ out, int n4)
{
    int i = blockIdx.x * blockDim.x + threadIdx.x;
    int stride = gridDim.x * blockDim.x;
    for (; i < n4; i += stride) {
        float4 v = in[i];
        v.x = rtf32(v.x); v.y = rtf32(v.y); v.z = rtf32(v.z); v.w = rtf32(v.w);
        out[i] = v;
    }
}

__global__ void __launch_bounds__(256)
softmax_kernel(float* __restrict__ S)
{
    __shared__ __align__(16) float row[T_];
    __shared__ float red[256];
    const size_t base = (size_t)blockIdx.x * T_;
    const int tid = threadIdx.x;

    float m = -1e30f;
    for (int i = tid; i < T_; i += 256) {
        float v = S[base + i];
        row[i] = v;
        m = fmaxf(m, v);
    }
    red[tid] = m;
    __syncthreads();
    #pragma unroll
    for (int s = 128; s > 0; s >>= 1) {
        if (tid < s) red[tid] = fmaxf(red[tid], red[tid + s]);
        __syncthreads();
    }
    m = red[0];
    __syncthreads();

    float sum = 0.0f;
    for (int i = tid; i < T_; i += 256) {
        float e = __expf(row[i] - m);
        row[i] = e;
        sum += e;
    }
    red[tid] = sum;
    __syncthreads();
    #pragma unroll
    for (int s = 128; s > 0; s >>= 1) {
        if (tid < s) red[tid] += red[tid + s];
        __syncthreads();
    }
    const float inv = 1.0f / red[0];
    for (int i = tid; i < T_; i += 256)
        S[base + i] = rtf32(row[i] * inv);    // rounded: next MMA input
}

// ---------------- host ----------------
extern "C" void kernel_launch(void* const* d_in, const int* in_sizes, int n_in,
                              void* d_out, int out_size)
{
    (void)in_sizes; (void)n_in; (void)out_size;
    const float* x  = (const float*)d_in[0];
    const float* Wq = (const float*)d_in[1];
    const float* Wk = (const float*)d_in[2];
    const float* Wv = (const float*)d_in[3];
    const float* Wo = (const float*)d_in[4];
    float* out = (float*)d_out;

    float *xr, *Wqr, *Wkr, *Wvr, *Wor, *Q, *K, *V, *Vt, *S, *O;
    cudaGetSymbolAddress((void**)&xr,  g_xr);
    cudaGetSymbolAddress((void**)&Wqr, g_Wqr);
    cudaGetSymbolAddress((void**)&Wkr, g_Wkr);
    cudaGetSymbolAddress((void**)&Wvr, g_Wvr);
    cudaGetSymbolAddress((void**)&Wor, g_Wor);
    cudaGetSymbolAddress((void**)&Q,   g_Q);
    cudaGetSymbolAddress((void**)&K,   g_K);
    cudaGetSymbolAddress((void**)&V,   g_V);
    cudaGetSymbolAddress((void**)&Vt,  g_Vt);
    cudaGetSymbolAddress((void**)&S,   g_S);
    cudaGetSymbolAddress((void**)&O,   g_O);

    const float inv_scale = 1.0f / sqrtf((float)HD);

    // round all MMA inputs to tf32 (unbiased rna)
    round_inputs<<<1024, 256>>>((const float4*)x,  (float4*)xr,  BT  * D_  / 4);
    round_inputs<<<1024, 256>>>((const float4*)Wq, (float4*)Wqr, D_  * D_  / 4);
    round_inputs<<<1024, 256>>>((const float4*)Wk, (float4*)Wkr, KVD * D_  / 4);
    round_inputs<<<1024, 256>>>((const float4*)Wv, (float4*)Wvr, KVD * D_  / 4);
    round_inputs<<<1024, 256>>>((const float4*)Wo, (float4*)Wor, D_  * D_  / 4);

    // projections (outputs rounded in epilogue: they feed later MMAs)
    gemm_tc<<<dim3(16, 32), 256>>>(xr, D_, Wqr, D_, Q, D_,  D_, 1.0f, 1);
    gemm_tc<<<dim3(8,  32), 256>>>(xr, D_, Wkr, D_, K, KVD, D_, 1.0f, 1);
    gemm_tc<<<dim3(8,  32), 256>>>(xr, D_, Wvr, D_, V, KVD, D_, 1.0f, 1);
    transpose_v<<<dim3(64, 32, 2), 256>>>(V, Vt);

    // attention
    scores_tc<<<dim3(16, 16, 32), 256>>>(Q, K, S, inv_scale);
    softmax_kernel<<<B_ * NH * T_, 256>>>(S);
    pv_tc<<<dim3(1, 16, 32), 256>>>(S, Vt, O);

    // output projection (final fp32 output, no rounding)
    gemm_tc<<<dim3(16, 32), 256>>>(O, D_, Wor, D_, out, D_, D_, 1.0f, 0);
}

// round 4
// speedup vs baseline: 3.3230x; 1.2891x over previous
#include <cuda_runtime.h>
#include <cstdint>
#include <math.h>

#define B_   2
#define T_   2048
#define D_   2048
#define NH   16
#define NKV  8
#define HD   128
#define KVD  1024
#define BT   4096

// ---------------- scratch (device globals; allocation-free) ----------------
__device__ float g_xr [(size_t)BT  * D_ ];
__device__ float g_Wqr[(size_t)D_  * D_ ];
__device__ float g_Wkr[(size_t)KVD * D_ ];
__device__ float g_Wvr[(size_t)KVD * D_ ];
__device__ float g_Wor[(size_t)D_  * D_ ];
__device__ float g_Q  [(size_t)BT  * D_ ];
__device__ float g_K  [(size_t)BT  * KVD];
__device__ float g_V  [(size_t)BT  * KVD];
__device__ float g_O  [(size_t)BT  * D_ ];

// ---------------- helpers ----------------
__device__ __forceinline__ uint32_t smem_u32(const void* p) {
    uint32_t a;
    asm("{ .reg .u64 t; cvta.to.shared.u64 t, %1; cvt.u32.u64 %0, t; }" : "=r"(a) : "l"(p));
    return a;
}
__device__ __forceinline__ float rtf32(float x) {
    uint32_t r; asm("cvt.rna.tf32.f32 %0, %1;" : "=r"(r) : "f"(x));
    return __uint_as_float(r);
}
__device__ __forceinline__ void cpa16(uint32_t dst, const float* src) {
    asm volatile("cp.async.cg.shared.global [%0], [%1], 16;" :: "r"(dst), "l"(src) : "memory");
}
__device__ __forceinline__ void mma_tf32(float* c, const uint32_t* a, const uint32_t* b) {
    asm volatile("mma.sync.aligned.m16n8k8.row.col.f32.tf32.tf32.f32 "
        "{%0,%1,%2,%3}, {%4,%5,%6,%7}, {%8,%9}, {%0,%1,%2,%3};"
        : "+f"(c[0]), "+f"(c[1]), "+f"(c[2]), "+f"(c[3])
        : "r"(a[0]), "r"(a[1]), "r"(a[2]), "r"(a[3]), "r"(b[0]), "r"(b[1]));
}

// ---------------------------------------------------------------------------
// tf32 MMA GEMM tile: C[128,128] = alpha * A @ B^T (A, B K-contiguous)
// ---------------------------------------------------------------------------
__device__ __forceinline__ void gemm_mma_body(
    const float* __restrict__ A, int lda,
    const float* __restrict__ B, int ldb,
    float* __restrict__ C, int ldc,
    int K, float alpha, bool round_out, int m0, int n0)
{
    __shared__ float As[2][128][20];
    __shared__ float Bs[2][128][20];

    const int tid  = threadIdx.x;
    const int lane = tid & 31;
    const int w    = tid >> 5;
    const int g    = lane >> 2;
    const int tg   = lane & 3;
    const int wm   = (w >> 2) << 6;
    const int wn   = (w & 3)  << 5;

    float acc[4][4][4];
    #pragma unroll
    for (int i = 0; i < 4; ++i)
        #pragma unroll
        for (int j = 0; j < 4; ++j)
            #pragma unroll
            for (int r = 0; r < 4; ++r)
                acc[i][j][r] = 0.0f;

    const float* Ab = A + (size_t)m0 * lda;
    const float* Bb = B + (size_t)n0 * ldb;
    const int nk = K >> 4;

    #pragma unroll
    for (int j = 0; j < 2; ++j) {
        int f = tid + (j << 8);
        int row = f >> 2, c4 = f & 3;
        cpa16(smem_u32(&As[0][row][0]) + c4 * 16, Ab + (size_t)row * lda + c4 * 4);
        cpa16(smem_u32(&Bs[0][row][0]) + c4 * 16, Bb + (size_t)row * ldb + c4 * 4);
    }
    asm volatile("cp.async.commit_group;" ::: "memory");

    for (int i = 0; i < nk; ++i) {
        const int b = i & 1;
        if (i + 1 < nk) {
            const int nb = b ^ 1;
            const int kt = (i + 1) << 4;
            #pragma unroll
            for (int j = 0; j < 2; ++j) {
                int f = tid + (j << 8);
                int row = f >> 2, c4 = f & 3;
                cpa16(smem_u32(&As[nb][row][0]) + c4 * 16, Ab + (size_t)row * lda + kt + c4 * 4);
                cpa16(smem_u32(&Bs[nb][row][0]) + c4 * 16, Bb + (size_t)row * ldb + kt + c4 * 4);
            }
            asm volatile("cp.async.commit_group;" ::: "memory");
            asm volatile("cp.async.wait_group 1;" ::: "memory");
        } else {
            asm volatile("cp.async.wait_group 0;" ::: "memory");
        }
        __syncthreads();

        #pragma unroll
        for (int ks = 0; ks < 2; ++ks) {
            const int k0 = ks << 3;
            uint32_t bf[4][2];
            #pragma unroll
            for (int nt = 0; nt < 4; ++nt) {
                bf[nt][0] = __float_as_uint(Bs[b][wn + (nt << 3) + g][k0 + tg]);
                bf[nt][1] = __float_as_uint(Bs[b][wn + (nt << 3) + g][k0 + tg + 4]);
            }
            #pragma unroll
            for (int mt = 0; mt < 4; ++mt) {
                uint32_t af[4];
                af[0] = __float_as_uint(As[b][wm + (mt << 4) + g    ][k0 + tg]);
                af[1] = __float_as_uint(As[b][wm + (mt << 4) + g + 8][k0 + tg]);
                af[2] = __float_as_uint(As[b][wm + (mt << 4) + g    ][k0 + tg + 4]);
                af[3] = __float_as_uint(As[b][wm + (mt << 4) + g + 8][k0 + tg + 4]);
                #pragma unroll
                for (int nt = 0; nt < 4; ++nt)
                    mma_tf32(acc[mt][nt], af, bf[nt]);
            }
        }
        __syncthreads();
    }

    #pragma unroll
    for (int mt = 0; mt < 4; ++mt) {
        const int r0 = m0 + wm + (mt << 4) + g;
        #pragma unroll
        for (int nt = 0; nt < 4; ++nt) {
            const int cb = n0 + wn + (nt << 3) + (tg << 1);
            float2 v0, v1;
            v0.x = acc[mt][nt][0] * alpha;  v0.y = acc[mt][nt][1] * alpha;
            v1.x = acc[mt][nt][2] * alpha;  v1.y = acc[mt][nt][3] * alpha;
            if (round_out) {
                v0.x = rtf32(v0.x); v0.y = rtf32(v0.y);
                v1.x = rtf32(v1.x); v1.y = rtf32(v1.y);
            }
            *(float2*)(C + (size_t)r0 * ldc + cb)       = v0;
            *(float2*)(C + (size_t)(r0 + 8) * ldc + cb) = v1;
        }
    }
}

__global__ void __launch_bounds__(256, 2)
gemm_tc(const float* __restrict__ A, int lda, const float* __restrict__ B, int ldb,
        float* __restrict__ C, int ldc, int K, float alpha, int round_out)
{
    gemm_mma_body(A, lda, B, ldb, C, ldc, K, alpha, round_out != 0,
                  blockIdx.y * 128, blockIdx.x * 128);
}

// ---------------------------------------------------------------------------
// Flash attention: CTA = 128 q-rows x one (b,hq). 8 warps x 16 rows.
// kv tile 64, cp.async double buffer. smem: K[2][64][132], V[2][64][136],
// P[8][16][68].  O accumulated in registers with online softmax.
// ---------------------------------------------------------------------------
#define SK_STRIDE 132
#define SV_STRIDE 136
#define SP_STRIDE 68
#define SK_BUF (64 * SK_STRIDE)   // 8448 floats
#define SV_BUF (64 * SV_STRIDE)   // 8704 floats
#define FLASH_SMEM ((2*SK_BUF + 2*SV_BUF + 8*16*SP_STRIDE) * 4)  // 172032 B

__global__ void __launch_bounds__(256, 1)
flash_attn(const float* __restrict__ Qg, const float* __restrict__ Kg,
           const float* __restrict__ Vg, float* __restrict__ Og)
{
    extern __shared__ float fsm[];
    float* sK = fsm;                       // 2 * 8448
    float* sV = fsm + 2 * SK_BUF;          // 2 * 8704
    float* sP = fsm + 2 * SK_BUF + 2 * SV_BUF;

    const int tid  = threadIdx.x;
    const int lane = tid & 31;
    const int w    = tid >> 5;
    const int g    = lane >> 2;
    const int tg   = lane & 3;
    const int z    = blockIdx.y, b = z >> 4, hq = z & 15, kv = hq >> 1;
    const int m0   = blockIdx.x << 7;
    const float inv_scale = 0.088388347648318447f;  // 1/sqrt(128)

    const size_t qbase = (size_t)b * T_ * D_  + (size_t)hq * HD;
    const size_t kbase = (size_t)b * T_ * KVD + (size_t)kv * HD;

    // ---- stage Q tile (128 x 128) through sK region, stride 132
    #pragma unroll
    for (int j = 0; j < 16; ++j) {
        int u = tid + (j << 8);
        int row = u >> 5, seg = (u & 31) << 2;
        cpa16(smem_u32(sK + row * SK_STRIDE + seg),
              Qg + qbase + (size_t)(m0 + row) * D_ + seg);
    }
    asm volatile("cp.async.commit_group;" ::: "memory");
    asm volatile("cp.async.wait_group 0;" ::: "memory");
    __syncthreads();

    uint32_t qf[16][4];
    {
        const float* qr0 = sK + (w * 16 + g) * SK_STRIDE;
        const float* qr1 = qr0 + 8 * SK_STRIDE;
        #pragma unroll
        for (int ks = 0; ks < 16; ++ks) {
            qf[ks][0] = __float_as_uint(qr0[ks * 8 + tg]);
            qf[ks][1] = __float_as_uint(qr1[ks * 8 + tg]);
            qf[ks][2] = __float_as_uint(qr0[ks * 8 + tg + 4]);
            qf[ks][3] = __float_as_uint(qr1[ks * 8 + tg + 4]);
        }
    }
    __syncthreads();

    float of[16][4];
    #pragma unroll
    for (int nt = 0; nt < 16; ++nt)
        #pragma unroll
        for (int r = 0; r < 4; ++r)
            of[nt][r] = 0.0f;
    float mprev0 = -1e30f, mprev1 = -1e30f, l0 = 0.0f, l1 = 0.0f;

    // ---- stage kv iter 0
    #pragma unroll
    for (int j = 0; j < 8; ++j) {
        int u = tid + (j << 8);
        int row = u >> 5, seg = (u & 31) << 2;
        cpa16(smem_u32(sK + row * SK_STRIDE + seg), Kg + kbase + (size_t)row * KVD + seg);
        cpa16(smem_u32(sV + row * SV_STRIDE + seg), Vg + kbase + (size_t)row * KVD + seg);
    }
    asm volatile("cp.async.commit_group;" ::: "memory");

    float* Pw = sP + w * 16 * SP_STRIDE;

    for (int it = 0; it < 32; ++it) {
        const int buf = it & 1;
        if (it + 1 < 32) {
            const int nb = buf ^ 1;
            const int t0 = (it + 1) << 6;
            #pragma unroll
            for (int j = 0; j < 8; ++j) {
                int u = tid + (j << 8);
                int row = u >> 5, seg = (u & 31) << 2;
                cpa16(smem_u32(sK + nb * SK_BUF + row * SK_STRIDE + seg),
                      Kg + kbase + (size_t)(t0 + row) * KVD + seg);
                cpa16(smem_u32(sV + nb * SV_BUF + row * SV_STRIDE + seg),
                      Vg + kbase + (size_t)(t0 + row) * KVD + seg);
            }
            asm volatile("cp.async.commit_group;" ::: "memory");
            asm volatile("cp.async.wait_group 1;" ::: "memory");
        } else {
            asm volatile("cp.async.wait_group 0;" ::: "memory");
        }
        __syncthreads();

        const float* Kb = sK + buf * SK_BUF;
        const float* Vb = sV + buf * SV_BUF;

        // S = Q @ K^T  (16 x 64 per warp)
        float sf[8][4];
        #pragma unroll
        for (int nt = 0; nt < 8; ++nt)
            sf[nt][0] = sf[nt][1] = sf[nt][2] = sf[nt][3] = 0.0f;
        #pragma unroll
        for (int ks = 0; ks < 16; ++ks) {
            const int k0 = ks << 3;
            #pragma unroll
            for (int nt = 0; nt < 8; ++nt) {
                uint32_t bb[2];
                const float* kr = Kb + (nt * 8 + g) * SK_STRIDE + k0;
                bb[0] = __float_as_uint(kr[tg]);
                bb[1] = __float_as_uint(kr[tg + 4]);
                mma_tf32(sf[nt], qf[ks], bb);
            }
        }

        // online softmax (thread rows: g and g+8 of warp tile)
        float mx0 = mprev0, mx1 = mprev1;
        #pragma unroll
        for (int nt = 0; nt < 8; ++nt) {
            sf[nt][0] *= inv_scale; sf[nt][1] *= inv_scale;
            sf[nt][2] *= inv_scale; sf[nt][3] *= inv_scale;
            mx0 = fmaxf(mx0, fmaxf(sf[nt][0], sf[nt][1]));
            mx1 = fmaxf(mx1, fmaxf(sf[nt][2], sf[nt][3]));
        }
        mx0 = fmaxf(mx0, __shfl_xor_sync(0xffffffffu, mx0, 1));
        mx0 = fmaxf(mx0, __shfl_xor_sync(0xffffffffu, mx0, 2));
        mx1 = fmaxf(mx1, __shfl_xor_sync(0xffffffffu, mx1, 1));
        mx1 = fmaxf(mx1, __shfl_xor_sync(0xffffffffu, mx1, 2));

        const float sc0 = __expf(mprev0 - mx0);
        const float sc1 = __expf(mprev1 - mx1);
        mprev0 = mx0; mprev1 = mx1;

        float rs0 = 0.0f, rs1 = 0.0f;
        #pragma unroll
        for (int nt = 0; nt < 8; ++nt) {
            float p0 = __expf(sf[nt][0] - mx0);
            float p1 = __expf(sf[nt][1] - mx0);
            float p2 = __expf(sf[nt][2] - mx1);
            float p3 = __expf(sf[nt][3] - mx1);
            rs0 += p0 + p1;  rs1 += p2 + p3;
            float2 st0 = make_float2(rtf32(p0), rtf32(p1));
            float2 st1 = make_float2(rtf32(p2), rtf32(p3));
            *(float2*)(Pw + g * SP_STRIDE + nt * 8 + 2 * tg)       = st0;
            *(float2*)(Pw + (g + 8) * SP_STRIDE + nt * 8 + 2 * tg) = st1;
        }
        rs0 += __shfl_xor_sync(0xffffffffu, rs0, 1);
        rs0 += __shfl_xor_sync(0xffffffffu, rs0, 2);
        rs1 += __shfl_xor_sync(0xffffffffu, rs1, 1);
        rs1 += __shfl_xor_sync(0xffffffffu, rs1, 2);
        l0 = l0 * sc0 + rs0;
        l1 = l1 * sc1 + rs1;

        #pragma unroll
        for (int nt = 0; nt < 16; ++nt) {
            of[nt][0] *= sc0; of[nt][1] *= sc0;
            of[nt][2] *= sc1; of[nt][3] *= sc1;
        }
        __syncwarp();

        // O += P @ V  (16 x 128 per warp)
        #pragma unroll
        for (int kc = 0; kc < 8; ++kc) {
            uint32_t aa[4];
            const float* pr0 = Pw + g * SP_STRIDE + kc * 8;
            const float* pr1 = Pw + (g + 8) * SP_STRIDE + kc * 8;
            aa[0] = __float_as_uint(pr0[tg]);
            aa[1] = __float_as_uint(pr1[tg]);
            aa[2] = __float_as_uint(pr0[tg + 4]);
            aa[3] = __float_as_uint(pr1[tg + 4]);
            const float* vr0 = Vb + (kc * 8 + tg) * SV_STRIDE + g;
            const float* vr1 = Vb + (kc * 8 + tg + 4) * SV_STRIDE + g;
            #pragma unroll
            for (int nt = 0; nt < 16; ++nt) {
                uint32_t bb[2];
                bb[0] = __float_as_uint(vr0[nt * 8]);
                bb[1] = __float_as_uint(vr1[nt * 8]);
                mma_tf32(of[nt], aa, bb);
            }
        }
        __syncthreads();
    }

    // epilogue: O /= l, round to tf32 (feeds out-proj MMA)
    const float i0 = 1.0f / l0;
    const float i1 = 1.0f / l1;
    const int r0 = m0 + w * 16 + g;
    const size_t obase = (size_t)b * T_ * D_ + (size_t)hq * HD;
    #pragma unroll
    for (int nt = 0; nt < 16; ++nt) {
        const int c = nt * 8 + 2 * tg;
        float2 v0 = make_float2(rtf32(of[nt][0] * i0), rtf32(of[nt][1] * i0));
        float2 v1 = make_float2(rtf32(of[nt][2] * i1), rtf32(of[nt][3] * i1));
        *(float2*)(Og + obase + (size_t)r0 * D_ + c)       = v0;
        *(float2*)(Og + obase + (size_t)(r0 + 8) * D_ + c) = v1;
    }
}

__global__ void __launch_bounds__(256)
round_inputs(const float4* __restrict__ in, float4* __restrict__ out, int n4)
{
    int i = blockIdx.x * blockDim.x + threadIdx.x;
    int stride = gridDim.x * blockDim.x;
    for (; i < n4; i += stride) {
        float4 v = in[i];
        v.x = rtf32(v.x); v.y = rtf32(v.y); v.z = rtf32(v.z); v.w = rtf32(v.w);
        out[i] = v;
    }
}

// ---------------- host ----------------
extern "C" void kernel_launch(void* const* d_in, const int* in_sizes, int n_in,
                              void* d_out, int out_size)
{
    (void)in_sizes; (void)n_in; (void)out_size;
    const float* x  = (const float*)d_in[0];
    const float* Wq = (const float*)d_in[1];
    const float* Wk = (const float*)d_in[2];
    const float* Wv = (const float*)d_in[3];
    const float* Wo = (const float*)d_in[4];
    float* out = (float*)d_out;

    float *xr, *Wqr, *Wkr, *Wvr, *Wor, *Q, *K, *V, *O;
    cudaGetSymbolAddress((void**)&xr,  g_xr);
    cudaGetSymbolAddress((void**)&Wqr, g_Wqr);
    cudaGetSymbolAddress((void**)&Wkr, g_Wkr);
    cudaGetSymbolAddress((void**)&Wvr, g_Wvr);
    cudaGetSymbolAddress((void**)&Wor, g_Wor);
    cudaGetSymbolAddress((void**)&Q,   g_Q);
    cudaGetSymbolAddress((void**)&K,   g_K);
    cudaGetSymbolAddress((void**)&V,   g_V);
    cudaGetSymbolAddress((void**)&O,   g_O);

    cudaFuncSetAttribute(flash_attn, cudaFuncAttributeMaxDynamicSharedMemorySize,
                         FLASH_SMEM);

    // round all MMA inputs to tf32 (unbiased rna)
    round_inputs<<<1024, 256>>>((const float4*)x,  (float4*)xr,  BT  * D_  / 4);
    round_inputs<<<1024, 256>>>((const float4*)Wq, (float4*)Wqr, D_  * D_  / 4);
    round_inputs<<<1024, 256>>>((const float4*)Wk, (float4*)Wkr, KVD * D_  / 4);
    round_inputs<<<1024, 256>>>((const float4*)Wv, (float4*)Wvr, KVD * D_  / 4);
    round_inputs<<<1024, 256>>>((const float4*)Wo, (float4*)Wor, D_  * D_  / 4);

    // projections (outputs rounded: they feed attention MMAs)
    gemm_tc<<<dim3(16, 32), 256>>>(xr, D_, Wqr, D_, Q, D_,  D_, 1.0f, 1);
    gemm_tc<<<dim3(8,  32), 256>>>(xr, D_, Wkr, D_, K, KVD, D_, 1.0f, 1);
    gemm_tc<<<dim3(8,  32), 256>>>(xr, D_, Wvr, D_, V, KVD, D_, 1.0f, 1);

    // fused attention (scores + softmax + PV)
    flash_attn<<<dim3(16, 32), 256, FLASH_SMEM>>>(Q, K, V, O);

    // output projection (final fp32 output, no rounding)
    gemm_tc<<<dim3(16, 32), 256>>>(O, D_, Wor, D_, out, D_, D_, 1.0f, 0);
}

// round 5
// speedup vs baseline: 3.4486x; 1.0378x over previous
#include <cuda_runtime.h>
#include <cstdint>
#include <math.h>

#define B_   2
#define T_   2048
#define D_   2048
#define NH   16
#define NKV  8
#define HD   128
#define KVD  1024
#define BT   4096

// ---------------- scratch (device globals; allocation-free) ----------------
__device__ float g_xr [(size_t)BT  * D_ ];
__device__ float g_Wqr[(size_t)D_  * D_ ];
__device__ float g_Wkr[(size_t)KVD * D_ ];
__device__ float g_Wvr[(size_t)KVD * D_ ];
__device__ float g_Wor[(size_t)D_  * D_ ];
__device__ float g_Q  [(size_t)BT  * D_ ];
__device__ float g_K  [(size_t)BT  * KVD];
__device__ float g_V  [(size_t)BT  * KVD];
__device__ float g_O  [(size_t)BT  * D_ ];

// ---------------- helpers ----------------
__device__ __forceinline__ uint32_t smem_u32(const void* p) {
    uint32_t a;
    asm("{ .reg .u64 t; cvta.to.shared.u64 t, %1; cvt.u32.u64 %0, t; }" : "=r"(a) : "l"(p));
    return a;
}
__device__ __forceinline__ float rtf32(float x) {
    uint32_t r; asm("cvt.rna.tf32.f32 %0, %1;" : "=r"(r) : "f"(x));
    return __uint_as_float(r);
}
__device__ __forceinline__ void cpa16(uint32_t dst, const float* src) {
    asm volatile("cp.async.cg.shared.global [%0], [%1], 16;" :: "r"(dst), "l"(src) : "memory");
}
__device__ __forceinline__ void mma_tf32(float* c, const uint32_t* a, const uint32_t* b) {
    asm volatile("mma.sync.aligned.m16n8k8.row.col.f32.tf32.tf32.f32 "
        "{%0,%1,%2,%3}, {%4,%5,%6,%7}, {%8,%9}, {%0,%1,%2,%3};"
        : "+f"(c[0]), "+f"(c[1]), "+f"(c[2]), "+f"(c[3])
        : "r"(a[0]), "r"(a[1]), "r"(a[2]), "r"(a[3]), "r"(b[0]), "r"(b[1]));
}

// ---------------------------------------------------------------------------
// tf32 MMA GEMM tile: C[128,128] = alpha * A @ B^T (A, B K-contiguous)
// 4-stage cp.async pipeline, ONE __syncthreads per 16-k chunk.
// Dynamic smem: As[4][128][20] + Bs[4][128][20] = 81920 B (2 CTAs/SM).
// ---------------------------------------------------------------------------
#define GROW 20
#define GBUF (128 * GROW)
#define GEMM_SMEM (4 * GBUF * 2 * 4)   // 81920 bytes

__device__ __forceinline__ void gemm_mma_body(
    const float* __restrict__ A, int lda,
    const float* __restrict__ B, int ldb,
    float* __restrict__ C, int ldc,
    int K, float alpha, bool round_out, int m0, int n0)
{
    extern __shared__ float gsm[];
    float* As = gsm;                 // 4 * 2560 floats
    float* Bs = gsm + 4 * GBUF;      // 4 * 2560 floats

    const int tid  = threadIdx.x;
    const int lane = tid & 31;
    const int w    = tid >> 5;
    const int g    = lane >> 2;
    const int tg   = lane & 3;
    const int wm   = (w >> 2) << 6;
    const int wn   = (w & 3)  << 5;

    float acc[4][4][4];
    #pragma unroll
    for (int i = 0; i < 4; ++i)
        #pragma unroll
        for (int j = 0; j < 4; ++j)
            #pragma unroll
            for (int r = 0; r < 4; ++r)
                acc[i][j][r] = 0.0f;

    const float* Ab = A + (size_t)m0 * lda;
    const float* Bb = B + (size_t)n0 * ldb;
    const int nk = K >> 4;

    // per-thread load coords: 512 cp.asyncs per chunk per array (2 per thread)
    const int r0 = tid >> 2, c0 = (tid & 3) << 2;            // j = 0
    const int r1 = (tid + 256) >> 2;                          // j = 1 (same c0)

    auto load_chunk = [&](int chunk) {
        const int st = chunk & 3;
        const int kt = chunk << 4;
        uint32_t aDst = smem_u32(As + st * GBUF);
        uint32_t bDst = smem_u32(Bs + st * GBUF);
        cpa16(aDst + (r0 * GROW + c0) * 4, Ab + (size_t)r0 * lda + kt + c0);
        cpa16(bDst + (r0 * GROW + c0) * 4, Bb + (size_t)r0 * ldb + kt + c0);
        cpa16(aDst + (r1 * GROW + c0) * 4, Ab + (size_t)r1 * lda + kt + c0);
        cpa16(bDst + (r1 * GROW + c0) * 4, Bb + (size_t)r1 * ldb + kt + c0);
        asm volatile("cp.async.commit_group;" ::: "memory");
    };

    // prologue: stages 0..2
    load_chunk(0);
    if (nk > 1) load_chunk(1);
    if (nk > 2) load_chunk(2);

    for (int i = 0; i < nk; ++i) {
        const int st = i & 3;
        const int rem = nk - 1 - i;
        if (rem >= 2)      asm volatile("cp.async.wait_group 2;" ::: "memory");
        else if (rem == 1) asm volatile("cp.async.wait_group 1;" ::: "memory");
        else               asm volatile("cp.async.wait_group 0;" ::: "memory");
        __syncthreads();                    // single barrier per chunk
        if (i + 3 < nk) load_chunk(i + 3);  // writes stage (i-1)&3: safe post-bar

        const float* Ac = As + st * GBUF;
        const float* Bc = Bs + st * GBUF;
        #pragma unroll
        for (int ks = 0; ks < 2; ++ks) {
            const int k0 = ks << 3;
            uint32_t bf[4][2];
            #pragma unroll
            for (int nt = 0; nt < 4; ++nt) {
                const float* br = Bc + (wn + (nt << 3) + g) * GROW + k0;
                bf[nt][0] = __float_as_uint(br[tg]);
                bf[nt][1] = __float_as_uint(br[tg + 4]);
            }
            #pragma unroll
            for (int mt = 0; mt < 4; ++mt) {
                const float* ar = Ac + (wm + (mt << 4) + g) * GROW + k0;
                uint32_t af[4];
                af[0] = __float_as_uint(ar[tg]);
                af[1] = __float_as_uint(ar[8 * GROW + tg]);
                af[2] = __float_as_uint(ar[tg + 4]);
                af[3] = __float_as_uint(ar[8 * GROW + tg + 4]);
                #pragma unroll
                for (int nt = 0; nt < 4; ++nt)
                    mma_tf32(acc[mt][nt], af, bf[nt]);
            }
        }
    }

    #pragma unroll
    for (int mt = 0; mt < 4; ++mt) {
        const int rr = m0 + wm + (mt << 4) + g;
        #pragma unroll
        for (int nt = 0; nt < 4; ++nt) {
            const int cb = n0 + wn + (nt << 3) + (tg << 1);
            float2 v0, v1;
            v0.x = acc[mt][nt][0] * alpha;  v0.y = acc[mt][nt][1] * alpha;
            v1.x = acc[mt][nt][2] * alpha;  v1.y = acc[mt][nt][3] * alpha;
            if (round_out) {
                v0.x = rtf32(v0.x); v0.y = rtf32(v0.y);
                v1.x = rtf32(v1.x); v1.y = rtf32(v1.y);
            }
            *(float2*)(C + (size_t)rr * ldc + cb)       = v0;
            *(float2*)(C + (size_t)(rr + 8) * ldc + cb) = v1;
        }
    }
}

__global__ void __launch_bounds__(256, 2)
gemm_tc(const float* __restrict__ A, int lda, const float* __restrict__ B, int ldb,
        float* __restrict__ C, int ldc, int K, float alpha, int round_out)
{
    gemm_mma_body(A, lda, B, ldb, C, ldc, K, alpha, round_out != 0,
                  blockIdx.y * 128, blockIdx.x * 128);
}

// ---------------------------------------------------------------------------
// Flash attention (unchanged from R4 — passing, near its cost model)
// ---------------------------------------------------------------------------
#define SK_STRIDE 132
#define SV_STRIDE 136
#define SP_STRIDE 68
#define SK_BUF (64 * SK_STRIDE)
#define SV_BUF (64 * SV_STRIDE)
#define FLASH_SMEM ((2*SK_BUF + 2*SV_BUF + 8*16*SP_STRIDE) * 4)

__global__ void __launch_bounds__(256, 1)
flash_attn(const float* __restrict__ Qg, const float* __restrict__ Kg,
           const float* __restrict__ Vg, float* __restrict__ Og)
{
    extern __shared__ float fsm[];
    float* sK = fsm;
    float* sV = fsm + 2 * SK_BUF;
    float* sP = fsm + 2 * SK_BUF + 2 * SV_BUF;

    const int tid  = threadIdx.x;
    const int lane = tid & 31;
    const int w    = tid >> 5;
    const int g    = lane >> 2;
    const int tg   = lane & 3;
    const int z    = blockIdx.y, b = z >> 4, hq = z & 15, kv = hq >> 1;
    const int m0   = blockIdx.x << 7;
    const float inv_scale = 0.088388347648318447f;

    const size_t qbase = (size_t)b * T_ * D_  + (size_t)hq * HD;
    const size_t kbase = (size_t)b * T_ * KVD + (size_t)kv * HD;

    #pragma unroll
    for (int j = 0; j < 16; ++j) {
        int u = tid + (j << 8);
        int row = u >> 5, seg = (u & 31) << 2;
        cpa16(smem_u32(sK + row * SK_STRIDE + seg),
              Qg + qbase + (size_t)(m0 + row) * D_ + seg);
    }
    asm volatile("cp.async.commit_group;" ::: "memory");
    asm volatile("cp.async.wait_group 0;" ::: "memory");
    __syncthreads();

    uint32_t qf[16][4];
    {
        const float* qr0 = sK + (w * 16 + g) * SK_STRIDE;
        const float* qr1 = qr0 + 8 * SK_STRIDE;
        #pragma unroll
        for (int ks = 0; ks < 16; ++ks) {
            qf[ks][0] = __float_as_uint(qr0[ks * 8 + tg]);
            qf[ks][1] = __float_as_uint(qr1[ks * 8 + tg]);
            qf[ks][2] = __float_as_uint(qr0[ks * 8 + tg + 4]);
            qf[ks][3] = __float_as_uint(qr1[ks * 8 + tg + 4]);
        }
    }
    __syncthreads();

    float of[16][4];
    #pragma unroll
    for (int nt = 0; nt < 16; ++nt)
        #pragma unroll
        for (int r = 0; r < 4; ++r)
            of[nt][r] = 0.0f;
    float mprev0 = -1e30f, mprev1 = -1e30f, l0 = 0.0f, l1 = 0.0f;

    #pragma unroll
    for (int j = 0; j < 8; ++j) {
        int u = tid + (j << 8);
        int row = u >> 5, seg = (u & 31) << 2;
        cpa16(smem_u32(sK + row * SK_STRIDE + seg), Kg + kbase + (size_t)row * KVD + seg);
        cpa16(smem_u32(sV + row * SV_STRIDE + seg), Vg + kbase + (size_t)row * KVD + seg);
    }
    asm volatile("cp.async.commit_group;" ::: "memory");

    float* Pw = sP + w * 16 * SP_STRIDE;

    for (int it = 0; it < 32; ++it) {
        const int buf = it & 1;
        if (it + 1 < 32) {
            const int nb = buf ^ 1;
            const int t0 = (it + 1) << 6;
            #pragma unroll
            for (int j = 0; j < 8; ++j) {
                int u = tid + (j << 8);
                int row = u >> 5, seg = (u & 31) << 2;
                cpa16(smem_u32(sK + nb * SK_BUF + row * SK_STRIDE + seg),
                      Kg + kbase + (size_t)(t0 + row) * KVD + seg);
                cpa16(smem_u32(sV + nb * SV_BUF + row * SV_STRIDE + seg),
                      Vg + kbase + (size_t)(t0 + row) * KVD + seg);
            }
            asm volatile("cp.async.commit_group;" ::: "memory");
            asm volatile("cp.async.wait_group 1;" ::: "memory");
        } else {
            asm volatile("cp.async.wait_group 0;" ::: "memory");
        }
        __syncthreads();

        const float* Kb = sK + buf * SK_BUF;
        const float* Vb = sV + buf * SV_BUF;

        float sf[8][4];
        #pragma unroll
        for (int nt = 0; nt < 8; ++nt)
            sf[nt][0] = sf[nt][1] = sf[nt][2] = sf[nt][3] = 0.0f;
        #pragma unroll
        for (int ks = 0; ks < 16; ++ks) {
            const int k0 = ks << 3;
            #pragma unroll
            for (int nt = 0; nt < 8; ++nt) {
                uint32_t bb[2];
                const float* kr = Kb + (nt * 8 + g) * SK_STRIDE + k0;
                bb[0] = __float_as_uint(kr[tg]);
                bb[1] = __float_as_uint(kr[tg + 4]);
                mma_tf32(sf[nt], qf[ks], bb);
            }
        }

        float mx0 = mprev0, mx1 = mprev1;
        #pragma unroll
        for (int nt = 0; nt < 8; ++nt) {
            sf[nt][0] *= inv_scale; sf[nt][1] *= inv_scale;
            sf[nt][2] *= inv_scale; sf[nt][3] *= inv_scale;
            mx0 = fmaxf(mx0, fmaxf(sf[nt][0], sf[nt][1]));
            mx1 = fmaxf(mx1, fmaxf(sf[nt][2], sf[nt][3]));
        }
        mx0 = fmaxf(mx0, __shfl_xor_sync(0xffffffffu, mx0, 1));
        mx0 = fmaxf(mx0, __shfl_xor_sync(0xffffffffu, mx0, 2));
        mx1 = fmaxf(mx1, __shfl_xor_sync(0xffffffffu, mx1, 1));
        mx1 = fmaxf(mx1, __shfl_xor_sync(0xffffffffu, mx1, 2));

        const float sc0 = __expf(mprev0 - mx0);
        const float sc1 = __expf(mprev1 - mx1);
        mprev0 = mx0; mprev1 = mx1;

        float rs0 = 0.0f, rs1 = 0.0f;
        #pragma unroll
        for (int nt = 0; nt < 8; ++nt) {
            float p0 = __expf(sf[nt][0] - mx0);
            float p1 = __expf(sf[nt][1] - mx0);
            float p2 = __expf(sf[nt][2] - mx1);
            float p3 = __expf(sf[nt][3] - mx1);
            rs0 += p0 + p1;  rs1 += p2 + p3;
            float2 st0 = make_float2(rtf32(p0), rtf32(p1));
            float2 st1 = make_float2(rtf32(p2), rtf32(p3));
            *(float2*)(Pw + g * SP_STRIDE + nt * 8 + 2 * tg)       = st0;
            *(float2*)(Pw + (g + 8) * SP_STRIDE + nt * 8 + 2 * tg) = st1;
        }
        rs0 += __shfl_xor_sync(0xffffffffu, rs0, 1);
        rs0 += __shfl_xor_sync(0xffffffffu, rs0, 2);
        rs1 += __shfl_xor_sync(0xffffffffu, rs1, 1);
        rs1 += __shfl_xor_sync(0xffffffffu, rs1, 2);
        l0 = l0 * sc0 + rs0;
        l1 = l1 * sc1 + rs1;

        #pragma unroll
        for (int nt = 0; nt < 16; ++nt) {
            of[nt][0] *= sc0; of[nt][1] *= sc0;
            of[nt][2] *= sc1; of[nt][3] *= sc1;
        }
        __syncwarp();

        #pragma unroll
        for (int kc = 0; kc < 8; ++kc) {
            uint32_t aa[4];
            const float* pr0 = Pw + g * SP_STRIDE + kc * 8;
            const float* pr1 = Pw + (g + 8) * SP_STRIDE + kc * 8;
            aa[0] = __float_as_uint(pr0[tg]);
            aa[1] = __float_as_uint(pr1[tg]);
            aa[2] = __float_as_uint(pr0[tg + 4]);
            aa[3] = __float_as_uint(pr1[tg + 4]);
            const float* vr0 = Vb + (kc * 8 + tg) * SV_STRIDE + g;
            const float* vr1 = Vb + (kc * 8 + tg + 4) * SV_STRIDE + g;
            #pragma unroll
            for (int nt = 0; nt < 16; ++nt) {
                uint32_t bb[2];
                bb[0] = __float_as_uint(vr0[nt * 8]);
                bb[1] = __float_as_uint(vr1[nt * 8]);
                mma_tf32(of[nt], aa, bb);
            }
        }
        __syncthreads();
    }

    const float i0 = 1.0f / l0;
    const float i1 = 1.0f / l1;
    const int r0 = m0 + w * 16 + g;
    const size_t obase = (size_t)b * T_ * D_ + (size_t)hq * HD;
    #pragma unroll
    for (int nt = 0; nt < 16; ++nt) {
        const int c = nt * 8 + 2 * tg;
        float2 v0 = make_float2(rtf32(of[nt][0] * i0), rtf32(of[nt][1] * i0));
        float2 v1 = make_float2(rtf32(of[nt][2] * i1), rtf32(of[nt][3] * i1));
        *(float2*)(Og + obase + (size_t)r0 * D_ + c)       = v0;
        *(float2*)(Og + obase + (size_t)(r0 + 8) * D_ + c) = v1;
    }
}

__global__ void __launch_bounds__(256)
round_inputs(const float4* __restrict__ in, float4* __restrict__ out, int n4)
{
    int i = blockIdx.x * blockDim.x + threadIdx.x;
    int stride = gridDim.x * blockDim.x;
    for (; i < n4; i += stride) {
        float4 v = in[i];
        v.x = rtf32(v.x); v.y = rtf32(v.y); v.z = rtf32(v.z); v.w = rtf32(v.w);
        out[i] = v;
    }
}

// ---------------- host ----------------
extern "C" void kernel_launch(void* const* d_in, const int* in_sizes, int n_in,
                              void* d_out, int out_size)
{
    (void)in_sizes; (void)n_in; (void)out_size;
    const float* x  = (const float*)d_in[0];
    const float* Wq = (const float*)d_in[1];
    const float* Wk = (const float*)d_in[2];
    const float* Wv = (const float*)d_in[3];
    const float* Wo = (const float*)d_in[4];
    float* out = (float*)d_out;

    float *xr, *Wqr, *Wkr, *Wvr, *Wor, *Q, *K, *V, *O;
    cudaGetSymbolAddress((void**)&xr,  g_xr);
    cudaGetSymbolAddress((void**)&Wqr, g_Wqr);
    cudaGetSymbolAddress((void**)&Wkr, g_Wkr);
    cudaGetSymbolAddress((void**)&Wvr, g_Wvr);
    cudaGetSymbolAddress((void**)&Wor, g_Wor);
    cudaGetSymbolAddress((void**)&Q,   g_Q);
    cudaGetSymbolAddress((void**)&K,   g_K);
    cudaGetSymbolAddress((void**)&V,   g_V);
    cudaGetSymbolAddress((void**)&O,   g_O);

    cudaFuncSetAttribute(gemm_tc, cudaFuncAttributeMaxDynamicSharedMemorySize,
                         GEMM_SMEM);
    cudaFuncSetAttribute(flash_attn, cudaFuncAttributeMaxDynamicSharedMemorySize,
                         FLASH_SMEM);

    // round all MMA inputs to tf32 (unbiased rna)
    round_inputs<<<1024, 256>>>((const float4*)x,  (float4*)xr,  BT  * D_  / 4);
    round_inputs<<<1024, 256>>>((const float4*)Wq, (float4*)Wqr, D_  * D_  / 4);
    round_inputs<<<1024, 256>>>((const float4*)Wk, (float4*)Wkr, KVD * D_  / 4);
    round_inputs<<<1024, 256>>>((const float4*)Wv, (float4*)Wvr, KVD * D_  / 4);
    round_inputs<<<1024, 256>>>((const float4*)Wo, (float4*)Wor, D_  * D_  / 4);

    // projections (outputs rounded: they feed attention MMAs)
    gemm_tc<<<dim3(16, 32), 256, GEMM_SMEM>>>(xr, D_, Wqr, D_, Q, D_,  D_, 1.0f, 1);
    gemm_tc<<<dim3(8,  32), 256, GEMM_SMEM>>>(xr, D_, Wkr, D_, K, KVD, D_, 1.0f, 1);
    gemm_tc<<<dim3(8,  32), 256, GEMM_SMEM>>>(xr, D_, Wvr, D_, V, KVD, D_, 1.0f, 1);

    // fused attention (scores + softmax + PV)
    flash_attn<<<dim3(16, 32), 256, FLASH_SMEM>>>(Q, K, V, O);

    // output projection (final fp32 output, no rounding)
    gemm_tc<<<dim3(16, 32), 256, GEMM_SMEM>>>(O, D_, Wor, D_, out, D_, D_, 1.0f, 0);
}